// round 4
// baseline (speedup 1.0000x reference)
#include <cuda_runtime.h>
#include <math.h>

typedef unsigned long long ull;

// ---------------- problem constants ----------------
constexpr int kB   = 2;
constexpr int kT   = 98304;
constexpr int kS   = 128;
constexpr int kHOP = 768;
constexpr int kNCB = 14;
constexpr int kDIM = 512;
constexpr int kVOC = 1024;
constexpr int kCH3 = kNCB * kDIM;   // 7168
constexpr long kL  = 97537;
constexpr int kBS  = kB * kS;       // 256
constexpr int kSPLIT = 4;
constexpr long BIGL = 1L << 40;

// ---------------- device scratch ----------------
__device__ float g_S1  [kBS * 1280];            // conv1 windows [m][c1*5+j]
__device__ float g_h2  [kBS * 512];
__device__ float g_X   [kBS * 1536];
__device__ float g_emb [kNCB * kBS * kDIM];     // [k][m][d]
__device__ float g_sc  [(long)kNCB * kBS * kVOC];
__device__ float g_cbn [kNCB * kVOC];
__device__ int   g_code[kNCB * kBS];
__device__ float g_q   [kBS * kCH3];
__device__ float g_C2p [kSPLIT * kBS * 2560];
__device__ float g_awin[kBS * 13 * 512];
__device__ float g_W2r [256 * 2560];
__device__ float g_C3  [kBS * 9 * 256];         // relu(conv2+db2) at specials
__device__ float g_bg2 [256];
__device__ float g_outbg;

// ---------------- f32x2 helpers ----------------
__device__ __forceinline__ void fma2(ull& acc, ull a, ull b) {
    asm("fma.rn.f32x2 %0, %1, %2, %0;" : "+l"(acc) : "l"(a), "l"(b));
}
__device__ __forceinline__ ull dup2(float x) {
    ull r; asm("mov.b64 %0, {%1, %1};" : "=l"(r) : "f"(x)); return r;
}
__device__ __forceinline__ void unpack2(ull v, float& lo, float& hi) {
    asm("mov.b64 {%0, %1}, %2;" : "=f"(lo), "=f"(hi) : "l"(v));
}

// ---------------- conv1 window builder ----------------
__global__ __launch_bounds__(256) void k_prep1(
    const float* __restrict__ audio, const float* __restrict__ ew1,
    const float* __restrict__ eb1) {
    int m = blockIdx.x; int b = m / kS, s = m % kS;
    int c1 = threadIdx.x;
    float wv[7];
    #pragma unroll
    for (int i = 0; i < 7; i++) wv[i] = ew1[c1 * 7 + i];
    float bias = eb1[c1];
    const float* au = audio + (long)b * kT;
    #pragma unroll
    for (int j = 0; j < 5; j++) {
        int p = s * kHOP - 2 + j;
        float v = 0.f;
        if (p >= 0 && p < kT) {
            float acc = bias;
            #pragma unroll
            for (int i = 0; i < 7; i++) {
                int x = p - 3 + i;
                float a = (x >= 0 && x < kT) ? au[x] : 0.f;
                acc = fmaf(wv[i], a, acc);
            }
            v = fmaxf(acc, 0.f);
        }
        g_S1[(long)m * 1280 + c1 * 5 + j] = v;
    }
}

// ---------------- im2col for enc conv3 (k=3, p=1) ----------------
__global__ void k_im2col() {
    int m = blockIdx.x; int b = m / kS, s = m % kS;
    for (int kk = threadIdx.x; kk < 1536; kk += blockDim.x) {
        int c2 = kk / 3, j = kk % 3;
        int s2 = s - 1 + j;
        float v = (s2 >= 0 && s2 < kS) ? g_h2[(long)(b * kS + s2) * 512 + c2] : 0.f;
        g_X[(long)m * 1536 + kk] = v;
    }
}

// ============== double-buffered f32x2 GEMM (64x64 tile, 128 thr) ==============
// Virtual A row m starts at A + (m/adiv)*aout + (m%adiv)*ain.
// z offsets: A+=z*zA, B+=z*zB, C+=z*zC, k range starts at z*zK.
// C write: Cb = C + (n0/cdiv)*cout; addr = Cb + mrow*ldc + n0%cdiv + col.
// Optional bias[n] (global n) and relu.

#define GEMM_PROLOG                                                          \
    __shared__ __align__(16) float As[2][16][72];                            \
    __shared__ __align__(16) float Bs[2][16][68];                            \
    int tid = threadIdx.x;                                                   \
    int m0 = blockIdx.y * 64, n0 = blockIdx.x * 64;                          \
    int tx = tid & 15, ty = tid >> 4;                                        \
    long kbase = (long)blockIdx.z * zK;                                      \
    ull acc[4][4];                                                           \
    _Pragma("unroll")                                                        \
    for (int i = 0; i < 4; i++)                                              \
        _Pragma("unroll")                                                    \
        for (int j = 0; j < 4; j++) acc[i][j] = 0ull;                        \
    int am = tid >> 1;                                                       \
    int akq = (tid & 1) * 8;                                                 \
    int mm = m0 + am;                                                        \
    long arowA = (long)(mm / adiv) * aout + (long)(mm % adiv) * ain;         \
    float4 ra0, ra1, rb0, rb1;

#define LOAD_A(k0v) {                                                        \
    long kg = kbase + (k0v) + akq;                                           \
    ra0 = *(const float4*)&A[arowA + kg];                                    \
    ra1 = *(const float4*)&A[arowA + kg + 4]; }

#define STORE_A(bufv) {                                                      \
    As[bufv][akq + 0][am] = ra0.x; As[bufv][akq + 1][am] = ra0.y;            \
    As[bufv][akq + 2][am] = ra0.z; As[bufv][akq + 3][am] = ra0.w;            \
    As[bufv][akq + 4][am] = ra1.x; As[bufv][akq + 5][am] = ra1.y;            \
    As[bufv][akq + 6][am] = ra1.z; As[bufv][akq + 7][am] = ra1.w; }

#define GEMM_COMPUTE(bufv)                                                   \
    _Pragma("unroll")                                                        \
    for (int k = 0; k < 16; k++) {                                           \
        ulonglong2 a01 = *(const ulonglong2*)&As[bufv][k][ty * 8];           \
        ulonglong2 a23 = *(const ulonglong2*)&As[bufv][k][ty * 8 + 4];       \
        float4 bv = *(const float4*)&Bs[bufv][k][tx * 4];                    \
        ull a_[4] = {a01.x, a01.y, a23.x, a23.y};                            \
        ull b_[4] = {dup2(bv.x), dup2(bv.y), dup2(bv.z), dup2(bv.w)};        \
        _Pragma("unroll")                                                    \
        for (int i = 0; i < 4; i++)                                          \
            _Pragma("unroll")                                                \
            for (int j = 0; j < 4; j++)                                      \
                fma2(acc[i][j], a_[i], b_[j]);                               \
    }

#define GEMM_MAIN(LOADB, STOREB)                                             \
    LOAD_A(0) LOADB(0)                                                       \
    STORE_A(0) STOREB(0)                                                     \
    __syncthreads();                                                         \
    int T = Klen / 16;                                                       \
    for (int t = 0; t < T; t++) {                                            \
        int cur = t & 1;                                                     \
        if (t + 1 < T) { LOAD_A((t + 1) * 16) LOADB((t + 1) * 16) }          \
        GEMM_COMPUTE(cur)                                                    \
        if (t + 1 < T) { STORE_A(1 - cur) STOREB(1 - cur) }                  \
        __syncthreads();                                                     \
    }

#define GEMM_EPILOG                                                          \
    float4 bv4 = make_float4(0.f, 0.f, 0.f, 0.f);                            \
    if (bias) bv4 = *(const float4*)&bias[n0 + tx * 4];                      \
    float* Cb = C + (long)(n0 / cdiv) * cout;                                \
    int nc = (int)(n0 % cdiv) + tx * 4;                                      \
    _Pragma("unroll")                                                        \
    for (int i = 0; i < 4; i++) {                                            \
        float lo0, hi0, lo1, hi1, lo2, hi2, lo3, hi3;                        \
        unpack2(acc[i][0], lo0, hi0); unpack2(acc[i][1], lo1, hi1);          \
        unpack2(acc[i][2], lo2, hi2); unpack2(acc[i][3], lo3, hi3);          \
        float4 v0 = make_float4(lo0 + bv4.x, lo1 + bv4.y, lo2 + bv4.z, lo3 + bv4.w); \
        float4 v1 = make_float4(hi0 + bv4.x, hi1 + bv4.y, hi2 + bv4.z, hi3 + bv4.w); \
        if (relu) {                                                          \
            v0.x = fmaxf(v0.x, 0.f); v0.y = fmaxf(v0.y, 0.f);                \
            v0.z = fmaxf(v0.z, 0.f); v0.w = fmaxf(v0.w, 0.f);                \
            v1.x = fmaxf(v1.x, 0.f); v1.y = fmaxf(v1.y, 0.f);                \
            v1.z = fmaxf(v1.z, 0.f); v1.w = fmaxf(v1.w, 0.f);                \
        }                                                                    \
        long mrow = m0 + ty * 8 + 2 * i;                                     \
        *(float4*)&Cb[mrow * ldc + nc] = v0;                                 \
        *(float4*)&Cb[(mrow + 1) * ldc + nc] = v1;                           \
    }

// B row-major [N, ldb]: C[m,n] = sum_k A(m)[k] * B[n][k]
__global__ __launch_bounds__(128) void gemm_nt(
    const float* __restrict__ A, const float* __restrict__ Bm,
    float* __restrict__ C, int Klen, int ldb,
    long adiv, long aout, long ain, long zA, long zB, long zC, long zK,
    int ldc, long cdiv, long cout, const float* __restrict__ bias, int relu) {
    A += blockIdx.z * zA; Bm += blockIdx.z * zB; C += blockIdx.z * zC;
    GEMM_PROLOG
    int bn = tid >> 1;
    int bkq = (tid & 1) * 8;
#define LOAD_B_NT(k0v) {                                                     \
    long kg = kbase + (k0v) + bkq;                                           \
    const float* bp = &Bm[(long)(n0 + bn) * ldb + kg];                       \
    rb0 = *(const float4*)bp; rb1 = *(const float4*)(bp + 4); }
#define STORE_B_NT(bufv) {                                                   \
    Bs[bufv][bkq + 0][bn] = rb0.x; Bs[bufv][bkq + 1][bn] = rb0.y;            \
    Bs[bufv][bkq + 2][bn] = rb0.z; Bs[bufv][bkq + 3][bn] = rb0.w;            \
    Bs[bufv][bkq + 4][bn] = rb1.x; Bs[bufv][bkq + 5][bn] = rb1.y;            \
    Bs[bufv][bkq + 6][bn] = rb1.z; Bs[bufv][bkq + 7][bn] = rb1.w; }
    GEMM_MAIN(LOAD_B_NT, STORE_B_NT)
    GEMM_EPILOG
}

// B row-major [K, ldb]: C[m,n] = sum_k A(m)[k] * B[k][n]
__global__ __launch_bounds__(128) void gemm_nn(
    const float* __restrict__ A, const float* __restrict__ Bm,
    float* __restrict__ C, int Klen, int ldb,
    long adiv, long aout, long ain, long zA, long zB, long zC, long zK,
    int ldc, long cdiv, long cout, const float* __restrict__ bias, int relu) {
    A += blockIdx.z * zA; Bm += blockIdx.z * zB; C += blockIdx.z * zC;
    GEMM_PROLOG
    int bk = tid >> 3;
    int bc = (tid & 7) * 4;
#define LOAD_B_NN(k0v) {                                                     \
    long kr = kbase + (k0v) + bk;                                            \
    const float* bp = &Bm[kr * (long)ldb + n0 + bc];                         \
    rb0 = *(const float4*)bp; rb1 = *(const float4*)(bp + 32); }
#define STORE_B_NN(bufv) {                                                   \
    *(float4*)&Bs[bufv][bk][bc] = rb0;                                       \
    *(float4*)&Bs[bufv][bk][bc + 32] = rb1; }
    GEMM_MAIN(LOAD_B_NN, STORE_B_NN)
    GEMM_EPILOG
}

// ---------------- VQ helpers ----------------
__global__ void k_cbnorm(const float* __restrict__ cb) {
    int row = blockIdx.x * 8 + (threadIdx.x >> 5);
    int lane = threadIdx.x & 31;
    const float* p = cb + (long)row * kDIM;
    float acc = 0.f;
    for (int d = lane; d < kDIM; d += 32) { float v = p[d]; acc = fmaf(v, v, acc); }
    #pragma unroll
    for (int o = 16; o > 0; o >>= 1) acc += __shfl_down_sync(0xffffffffu, acc, o);
    if (!lane) g_cbn[row] = acc;
}

__global__ void k_argmin() {
    int row = blockIdx.x;
    int k = row / kBS;
    const float* sc = g_sc + (long)row * kVOC;
    const float* cn = g_cbn + k * kVOC;
    float best = 3.4e38f; int bi = 0;
    for (int v = threadIdx.x; v < kVOC; v += 256) {
        float d = cn[v] - 2.f * sc[v];
        if (d < best) { best = d; bi = v; }
    }
    __shared__ float sv[256]; __shared__ int si[256];
    sv[threadIdx.x] = best; si[threadIdx.x] = bi;
    __syncthreads();
    for (int st = 128; st > 0; st >>= 1) {
        if (threadIdx.x < st) {
            float o = sv[threadIdx.x + st]; int oi = si[threadIdx.x + st];
            if (o < sv[threadIdx.x] || (o == sv[threadIdx.x] && oi < si[threadIdx.x])) {
                sv[threadIdx.x] = o; si[threadIdx.x] = oi;
            }
        }
        __syncthreads();
    }
    if (!threadIdx.x) g_code[row] = si[0];
}

__global__ void k_gather(const float* __restrict__ cb) {
    int m = blockIdx.x;
    for (int n = threadIdx.x * 4; n < kCH3; n += blockDim.x * 4) {
        int k = n >> 9, d = n & 511;
        int code = g_code[k * kBS + m];
        *(float4*)&g_q[(long)m * kCH3 + n] =
            *(const float4*)&cb[((long)k * kVOC + code) * kDIM + d];
    }
}

// ---------------- decoder helpers ----------------
__global__ void k_w2r(const float* __restrict__ dw2) {
    long i = (long)blockIdx.x * blockDim.x + threadIdx.x;
    if (i < 256L * 2560) {
        int cp = (int)(i / 2560), r = (int)(i % 2560);
        int jj = r / 512, c = r % 512;
        g_W2r[i] = dw2[(long)cp * 2560 + c * 5 + jj];
    }
}

__global__ void k_awin(const float* __restrict__ db1) {
    int m = blockIdx.x; int s = m % kS;
    const long SP = (long)kBS * 2560;
    for (int i = threadIdx.x; i < 13 * 512; i += blockDim.x) {
        int off = i / 512 - 6; int o = i & 511;
        long t = (long)s * kHOP + off;
        float v = 0.f;
        if (t >= 0 && t < kL) {
            if (off >= -2 && off <= 2) {
                long idx = (long)m * 2560 + o * 5 + (off + 2);
                float c2 = g_C2p[idx] + g_C2p[idx + SP] + g_C2p[idx + 2 * SP] + g_C2p[idx + 3 * SP];
                v = fmaxf(c2 + db1[o], 0.f);
            } else
                v = fmaxf(db1[o], 0.f);
        }
        g_awin[(long)m * 6656 + i] = v;
    }
}

__global__ void k_bg2(const float* __restrict__ dw2, const float* __restrict__ db1,
                      const float* __restrict__ db2) {
    int cp = blockIdx.x, tid = threadIdx.x;
    float acc = 0.f;
    for (int kk = tid; kk < 2560; kk += 256)
        acc = fmaf(dw2[(long)cp * 2560 + kk], fmaxf(db1[kk / 5], 0.f), acc);
    __shared__ float red[256];
    red[tid] = acc; __syncthreads();
    for (int st = 128; st; st >>= 1) { if (tid < st) red[tid] += red[tid + st]; __syncthreads(); }
    if (!tid) g_bg2[cp] = fmaxf(red[0] + db2[cp], 0.f);
}

__global__ void k_outbg(const float* __restrict__ dw3, const float* __restrict__ db3) {
    __shared__ float red[256];
    int c = threadIdx.x;
    float a = 0.f;
    #pragma unroll
    for (int j = 0; j < 7; j++) a += dw3[c * 7 + j];
    red[c] = a * g_bg2[c];
    __syncthreads();
    for (int st = 128; st; st >>= 1) { if (c < st) red[c] += red[c + st]; __syncthreads(); }
    if (!c) g_outbg = tanhf(red[0] + db3[0]);
}

__global__ void k_fill(float* __restrict__ out, long n) {
    long i = (long)blockIdx.x * 256 + threadIdx.x;
    if (i < n) out[i] = g_outbg;
}

__global__ __launch_bounds__(256) void k_final(
    float* __restrict__ out,
    const float* __restrict__ dw3, const float* __restrict__ db3) {
    int m = blockIdx.x; int b = m / kS, s = m % kS;
    int tid = threadIdx.x;
    int g = tid >> 4, l = tid & 15;
    int r3 = g - 7;
    long t = (long)s * kHOP + r3;
    bool active = (g < 15) && t >= 0 && t < kL;
    float acc = 0.f;
    if (g < 15) {
        for (int c = l; c < 256; c += 16) {
            #pragma unroll
            for (int j = 0; j < 7; j++) {
                int off = r3 - 3 + j;
                long tt = (long)s * kHOP + off;
                float a2;
                if (tt < 0 || tt >= kL) a2 = 0.f;
                else if (off >= -4 && off <= 4)
                    a2 = g_C3[((long)m * 9 + off + 4) * 256 + c];   // already relu(conv2+db2)
                else a2 = g_bg2[c];
                acc = fmaf(dw3[c * 7 + j], a2, acc);
            }
        }
    }
    #pragma unroll
    for (int o = 8; o > 0; o >>= 1) acc += __shfl_down_sync(0xffffffffu, acc, o, 16);
    if (active && l == 0) out[(long)b * kL + t] = tanhf(acc + db3[0]);
}

// ---------------- launch ----------------
extern "C" void kernel_launch(void* const* d_in, const int* in_sizes, int n_in,
                              void* d_out, int out_size) {
    const float* audio = (const float*)d_in[0];
    const float* cb    = (const float*)d_in[1];
    const float* ew1   = (const float*)d_in[2];
    const float* eb1   = (const float*)d_in[3];
    const float* ew2   = (const float*)d_in[4];
    const float* eb2   = (const float*)d_in[5];
    const float* ew3   = (const float*)d_in[6];
    const float* eb3   = (const float*)d_in[7];
    const float* dw1   = (const float*)d_in[8];
    const float* db1   = (const float*)d_in[9];
    const float* dw2   = (const float*)d_in[10];
    const float* db2   = (const float*)d_in[11];
    const float* dw3   = (const float*)d_in[12];
    const float* db3   = (const float*)d_in[13];
    float* out = (float*)d_out;

    void *pS1, *pH2, *pX, *pEmb, *pSc, *pQ, *pC2p, *pAwin, *pW2r, *pC3;
    cudaGetSymbolAddress(&pS1, g_S1);
    cudaGetSymbolAddress(&pH2, g_h2);
    cudaGetSymbolAddress(&pX, g_X);
    cudaGetSymbolAddress(&pEmb, g_emb);
    cudaGetSymbolAddress(&pSc, g_sc);
    cudaGetSymbolAddress(&pQ, g_q);
    cudaGetSymbolAddress(&pC2p, g_C2p);
    cudaGetSymbolAddress(&pAwin, g_awin);
    cudaGetSymbolAddress(&pW2r, g_W2r);
    cudaGetSymbolAddress(&pC3, g_C3);

    // weight-only prep (no deps)
    k_cbnorm<<<kNCB * kVOC / 8, 256>>>(cb);
    k_w2r<<<(256 * 2560 + 255) / 256, 256>>>(dw2);
    k_bg2<<<256, 256>>>(dw2, db1, db2);
    k_outbg<<<1, 256>>>(dw3, db3);
    k_fill<<<(int)((kB * kL + 255) / 256), 256>>>(out, kB * kL);

    // encoder: conv1 windows -> GEMM conv2 (bias+relu) -> im2col -> GEMM conv3
    k_prep1<<<kBS, 256>>>(audio, ew1, eb1);
    gemm_nt<<<dim3(512 / 64, kBS / 64, 1), 128>>>(
        (const float*)pS1, ew2, (float*)pH2, 1280, 1280,
        BIGL, 0, 1280, 0, 0, 0, 0, 512, BIGL, 0, eb2, 1);
    k_im2col<<<kBS, 256>>>();
    // writes straight into g_emb [k][m][d] layout with eb3 fused
    gemm_nt<<<dim3(kCH3 / 64, kBS / 64, 1), 128>>>(
        (const float*)pX, ew3, (float*)pEmb, 1536, 1536,
        BIGL, 0, 1536, 0, 0, 0, 0, 512, 512, (long)kBS * 512, eb3, 0);

    // VQ
    gemm_nt<<<dim3(kVOC / 64, kBS / 64, kNCB), 128>>>(
        (const float*)pEmb, cb, (float*)pSc, kDIM, kDIM,
        BIGL, 0, kDIM, (long)kBS * kDIM, (long)kVOC * kDIM, (long)kBS * kVOC, 0,
        kVOC, BIGL, 0, nullptr, 0);
    k_argmin<<<kNCB * kBS, 256>>>();
    k_gather<<<kBS, 256>>>(cb);

    // decoder conv_transpose specials, split-K=4
    gemm_nn<<<dim3(2560 / 64, kBS / 64, kSPLIT), 128>>>(
        (const float*)pQ, dw1, (float*)pC2p, kCH3 / kSPLIT, 2560,
        BIGL, 0, kCH3, 0, 0, (long)kBS * 2560, kCH3 / kSPLIT,
        2560, BIGL, 0, nullptr, 0);

    // decoder conv2 specials (bias db2 + relu fused)
    k_awin<<<kBS, 256>>>(db1);
    gemm_nt<<<dim3(256 / 64, kBS * 9 / 64, 1), 128>>>(
        (const float*)pAwin, (const float*)pW2r, (float*)pC3, 2560, 2560,
        9, 6656, 512, 0, 0, 0, 0, 256, BIGL, 0, db2, 1);

    // final conv3 specials
    k_final<<<kBS, 256>>>(out, dw3, db3);
}

// round 6
// speedup vs baseline: 2.0665x; 2.0665x over previous
#include <cuda_runtime.h>
#include <math.h>
#include <stdint.h>

// ---------------- problem constants ----------------
constexpr int kB = 2, kT = 98304, kS = 128, kHOP = 768, kNCB = 14;
constexpr int kDIM = 512, kVOC = 1024, kCH3 = kNCB * kDIM;   // 7168
constexpr long kL = 97537;
constexpr int kBS = kB * kS;        // 256
constexpr long BIGL = 1L << 40;

// ---------------- device scratch ----------------
__device__ float g_S1  [kBS * 1280];
__device__ float g_h2p [8 * kBS * 512];
__device__ float g_h2  [kBS * 512];
__device__ float g_X   [kBS * 1536];
__device__ float g_emb [kNCB * kBS * kDIM];
__device__ float g_sc  [(long)kNCB * kBS * kVOC];
__device__ float g_cbn [kNCB * kVOC];
__device__ int   g_code[kNCB * kBS];
__device__ float g_q   [kBS * kCH3];
__device__ float g_C2p [4 * kBS * 2560];
__device__ float g_awin[kBS * 13 * 512];
__device__ float g_W2r [256 * 2560];
__device__ float g_C3p [4 * 2304 * 256];
__device__ float g_C3  [2304 * 256];
__device__ float g_bg2 [256];
__device__ float g_outbg;

// =================== HMMA bf16 split-precision GEMM ===================
// CTA tile 128x128, 8 warps of 64x32, K-chunk 32. A/B stored in smem as bf16
// hi/lo pairs, row pitch 80B. 3 mma passes (hh, hl, lh) -> fp32 acc.
constexpr int KC = 32;
constexpr int PITCH_B = 80;                  // bytes per row (40 bf16)
constexpr int TILE_BYTES = 128 * PITCH_B;    // 10240 per (matrix, h-or-l)
constexpr int STAGE = 4 * TILE_BYTES;        // Ah, Al, Bh, Bl
constexpr int SMEM_DYN = 2 * STAGE;          // 81920

__device__ __forceinline__ uint32_t s2u(const void* p) {
    uint32_t a;
    asm("{ .reg .u64 t; cvta.to.shared.u64 t, %1; cvt.u32.u64 %0, t; }" : "=r"(a) : "l"(p));
    return a;
}
__device__ __forceinline__ uint32_t pkbf2(float lo, float hi) {
    uint32_t r;
    asm("cvt.rn.bf16x2.f32 %0, %1, %2;" : "=r"(r) : "f"(hi), "f"(lo));
    return r;
}
// 8 f32 -> 8 bf16 hi + 8 bf16 lo (x ~= hi + lo)
__device__ __forceinline__ void cvt8(float4 x0, float4 x1, uint4& h, uint4& l) {
    h.x = pkbf2(x0.x, x0.y); h.y = pkbf2(x0.z, x0.w);
    h.z = pkbf2(x1.x, x1.y); h.w = pkbf2(x1.z, x1.w);
    l.x = pkbf2(x0.x - __uint_as_float(h.x << 16), x0.y - __uint_as_float(h.x & 0xffff0000u));
    l.y = pkbf2(x0.z - __uint_as_float(h.y << 16), x0.w - __uint_as_float(h.y & 0xffff0000u));
    l.z = pkbf2(x1.x - __uint_as_float(h.z << 16), x1.y - __uint_as_float(h.z & 0xffff0000u));
    l.w = pkbf2(x1.z - __uint_as_float(h.w << 16), x1.w - __uint_as_float(h.w & 0xffff0000u));
}
__device__ __forceinline__ void ldsm4(uint32_t a, uint32_t& r0, uint32_t& r1,
                                      uint32_t& r2, uint32_t& r3) {
    asm volatile("ldmatrix.sync.aligned.m8n8.x4.shared.b16 {%0,%1,%2,%3},[%4];"
                 : "=r"(r0), "=r"(r1), "=r"(r2), "=r"(r3) : "r"(a));
}
__device__ __forceinline__ void mma16816(float* d, const uint32_t* a, const uint32_t* b) {
    asm volatile(
        "mma.sync.aligned.m16n8k16.row.col.f32.bf16.bf16.f32 "
        "{%0,%1,%2,%3},{%4,%5,%6,%7},{%8,%9},{%0,%1,%2,%3};"
        : "+f"(d[0]), "+f"(d[1]), "+f"(d[2]), "+f"(d[3])
        : "r"(a[0]), "r"(a[1]), "r"(a[2]), "r"(a[3]), "r"(b[0]), "r"(b[1]));
}

// C[m,n] = sum_k A(m)[k]*B(n,k).  BNN=0: B[N,ldb] row-major (reads B[n][k]);
// BNN=1: B[K,ldb] row-major (reads B[k][n]).
// A row m base = (m/adiv)*aout + (m%adiv)*ain.  z: A+=z*zA, B+=z*zB, C+=z*zC, kbase=z*zK.
// C: Cb = C + (n0/cdiv)*cout; element [mrow*ldc + n0%cdiv + col]. bias[n] global, optional relu.
template <int BNN>
__global__ __launch_bounds__(256, 1)
void hmma_gemm(const float* __restrict__ A, const float* __restrict__ B,
               float* __restrict__ C, int Klen, int ldb,
               long adiv, long aout, long ain, long zA, long zB, long zC, long zK,
               int ldc, long cdiv, long cout, const float* __restrict__ bias, int relu) {
    extern __shared__ __align__(16) char smem[];
    A += (long)blockIdx.z * zA; B += (long)blockIdx.z * zB; C += (long)blockIdx.z * zC;
    long kbase = (long)blockIdx.z * zK;
    int m0 = blockIdx.y * 128, n0 = blockIdx.x * 128;
    int tid = threadIdx.x, lane = tid & 31, wid = tid >> 5;
    int wm = wid & 1, wn = wid >> 1;       // warp tile: rows wm*64, cols wn*32
    uint32_t sbase = s2u(smem);

    // A producer indexing: row = (tid>>2)+i*64, k-octet = tid&3
    int akg = tid & 3, ar = tid >> 2;
    long arow[2];
    #pragma unroll
    for (int i = 0; i < 2; i++) {
        long m = m0 + ar + i * 64;
        arow[i] = (m / adiv) * aout + (m % adiv) * ain;
    }
    // B producer indexing
    int bkg = tid & 3, br = tid >> 2;      // NT path
    int bn = tid & 127, bkq = tid >> 7;    // NN path

    float acc[4][4][4];
    #pragma unroll
    for (int i = 0; i < 4; i++)
        #pragma unroll
        for (int j = 0; j < 4; j++)
            #pragma unroll
            for (int r = 0; r < 4; r++) acc[i][j][r] = 0.f;

    float4 sa[2][2];            // A staging: 2 rows x 8 floats
    float4 sb[2][2];            // B NT staging
    float  sx[16];              // B NN staging

#define LOADA(kc) {                                                          \
    _Pragma("unroll")                                                        \
    for (int i = 0; i < 2; i++) {                                            \
        const float* p = A + arow[i] + (kc) + akg * 8;                       \
        sa[i][0] = *(const float4*)p; sa[i][1] = *(const float4*)(p + 4);    \
    } }
#define STSA(buf) {                                                          \
    _Pragma("unroll")                                                        \
    for (int i = 0; i < 2; i++) {                                            \
        uint4 h, l; cvt8(sa[i][0], sa[i][1], h, l);                          \
        uint32_t off = sbase + (buf) * STAGE + (ar + i * 64) * PITCH_B + akg * 16; \
        *(uint4*)(size_t)0; (void)0;                                         \
        asm volatile("st.shared.v4.b32 [%0],{%1,%2,%3,%4};" ::               \
            "r"(off), "r"(h.x), "r"(h.y), "r"(h.z), "r"(h.w));               \
        asm volatile("st.shared.v4.b32 [%0],{%1,%2,%3,%4};" ::               \
            "r"(off + TILE_BYTES), "r"(l.x), "r"(l.y), "r"(l.z), "r"(l.w));  \
    } }
#define LOADB_NT(kc) {                                                       \
    _Pragma("unroll")                                                        \
    for (int i = 0; i < 2; i++) {                                            \
        const float* p = B + (long)(n0 + br + i * 64) * ldb + (kc) + bkg * 8; \
        sb[i][0] = *(const float4*)p; sb[i][1] = *(const float4*)(p + 4);    \
    } }
#define STSB_NT(buf) {                                                       \
    _Pragma("unroll")                                                        \
    for (int i = 0; i < 2; i++) {                                            \
        uint4 h, l; cvt8(sb[i][0], sb[i][1], h, l);                          \
        uint32_t off = sbase + (buf) * STAGE + 2 * TILE_BYTES                \
                     + (br + i * 64) * PITCH_B + bkg * 16;                   \
        asm volatile("st.shared.v4.b32 [%0],{%1,%2,%3,%4};" ::               \
            "r"(off), "r"(h.x), "r"(h.y), "r"(h.z), "r"(h.w));               \
        asm volatile("st.shared.v4.b32 [%0],{%1,%2,%3,%4};" ::               \
            "r"(off + TILE_BYTES), "r"(l.x), "r"(l.y), "r"(l.z), "r"(l.w));  \
    } }
#define LOADB_NN(kc) {                                                       \
    _Pragma("unroll")                                                        \
    for (int j = 0; j < 16; j++)                                             \
        sx[j] = B[((kc) + bkq * 16 + j) * (long)ldb + n0 + bn];              \
    }
#define STSB_NN(buf) {                                                       \
    uint32_t off = sbase + (buf) * STAGE + 2 * TILE_BYTES                    \
                 + bn * PITCH_B + bkq * 32;                                  \
    uint4 h, l;                                                              \
    cvt8(make_float4(sx[0], sx[1], sx[2], sx[3]),                            \
         make_float4(sx[4], sx[5], sx[6], sx[7]), h, l);                     \
    asm volatile("st.shared.v4.b32 [%0],{%1,%2,%3,%4};" ::                   \
        "r"(off), "r"(h.x), "r"(h.y), "r"(h.z), "r"(h.w));                   \
    asm volatile("st.shared.v4.b32 [%0],{%1,%2,%3,%4};" ::                   \
        "r"(off + TILE_BYTES), "r"(l.x), "r"(l.y), "r"(l.z), "r"(l.w));      \
    cvt8(make_float4(sx[8], sx[9], sx[10], sx[11]),                          \
         make_float4(sx[12], sx[13], sx[14], sx[15]), h, l);                 \
    asm volatile("st.shared.v4.b32 [%0],{%1,%2,%3,%4};" ::                   \
        "r"(off + 16), "r"(h.x), "r"(h.y), "r"(h.z), "r"(h.w));              \
    asm volatile("st.shared.v4.b32 [%0],{%1,%2,%3,%4};" ::                   \
        "r"(off + TILE_BYTES + 16), "r"(l.x), "r"(l.y), "r"(l.z), "r"(l.w)); \
    }

    // prologue: fill buffer 0
    LOADA(kbase)
    if (!BNN) { LOADB_NT(kbase) } else { LOADB_NN(kbase) }
    STSA(0)
    if (!BNN) { STSB_NT(0) } else { STSB_NN(0) }
    __syncthreads();

    int T = Klen / KC;
    int j8 = lane >> 3, r8 = lane & 7;
    for (int t = 0; t < T; t++) {
        int cur = t & 1;
        if (t + 1 < T) {
            long kc = kbase + (long)(t + 1) * KC;
            LOADA(kc)
            if (!BNN) { LOADB_NT(kc) } else { LOADB_NN(kc) }
        }
        uint32_t uA = sbase + cur * STAGE;
        uint32_t uB = uA + 2 * TILE_BYTES;
        #pragma unroll
        for (int ks = 0; ks < 2; ks++) {
            uint32_t ah[4][4], al[4][4], bh[4][2], bl[4][2];
            #pragma unroll
            for (int mf = 0; mf < 4; mf++) {
                uint32_t off = (uint32_t)((wm * 64 + mf * 16 + ((j8 & 1) << 3) + r8) * PITCH_B
                                          + ks * 32 + ((j8 >> 1) << 4));
                ldsm4(uA + off, ah[mf][0], ah[mf][1], ah[mf][2], ah[mf][3]);
                ldsm4(uA + TILE_BYTES + off, al[mf][0], al[mf][1], al[mf][2], al[mf][3]);
            }
            #pragma unroll
            for (int fp = 0; fp < 2; fp++) {
                uint32_t off = (uint32_t)((wn * 32 + fp * 16 + ((j8 >> 1) << 3) + r8) * PITCH_B
                                          + ks * 32 + ((j8 & 1) << 4));
                uint32_t t0, t1, t2, t3;
                ldsm4(uB + off, t0, t1, t2, t3);
                bh[fp * 2][0] = t0; bh[fp * 2][1] = t1;
                bh[fp * 2 + 1][0] = t2; bh[fp * 2 + 1][1] = t3;
                ldsm4(uB + TILE_BYTES + off, t0, t1, t2, t3);
                bl[fp * 2][0] = t0; bl[fp * 2][1] = t1;
                bl[fp * 2 + 1][0] = t2; bl[fp * 2 + 1][1] = t3;
            }
            #pragma unroll
            for (int mf = 0; mf < 4; mf++)
                #pragma unroll
                for (int nf = 0; nf < 4; nf++) {
                    mma16816(acc[mf][nf], ah[mf], bh[nf]);
                    mma16816(acc[mf][nf], ah[mf], bl[nf]);
                    mma16816(acc[mf][nf], al[mf], bh[nf]);
                }
        }
        if (t + 1 < T) {
            STSA(1 - cur)
            if (!BNN) { STSB_NT(1 - cur) } else { STSB_NN(1 - cur) }
        }
        __syncthreads();
    }

    // epilogue: fp32 frags -> C with virtual mapping + bias + relu
    float* Cb = C + (long)(n0 / cdiv) * cout;
    long ncb0 = n0 % cdiv;
    int mrow_base = m0 + wm * 64 + (lane >> 2);
    int ncol_base = wn * 32 + (lane & 3) * 2;
    #pragma unroll
    for (int mf = 0; mf < 4; mf++)
        #pragma unroll
        for (int nf = 0; nf < 4; nf++) {
            int ncol = ncol_base + nf * 8;
            float bx = 0.f, by = 0.f;
            if (bias) { bx = bias[n0 + ncol]; by = bias[n0 + ncol + 1]; }
            #pragma unroll
            for (int h = 0; h < 2; h++) {
                float vx = acc[mf][nf][h * 2 + 0] + bx;
                float vy = acc[mf][nf][h * 2 + 1] + by;
                if (relu) { vx = fmaxf(vx, 0.f); vy = fmaxf(vy, 0.f); }
                long row = mrow_base + mf * 16 + h * 8;
                float2 v = make_float2(vx, vy);
                *(float2*)&Cb[row * (long)ldc + ncb0 + ncol] = v;
            }
        }
}

// ---------------- small kernels ----------------
__global__ __launch_bounds__(256) void k_prep1(
    const float* __restrict__ audio, const float* __restrict__ ew1, const float* __restrict__ eb1) {
    int m = blockIdx.x; int b = m / kS, s = m % kS;
    int c1 = threadIdx.x;
    float wv[7];
    #pragma unroll
    for (int i = 0; i < 7; i++) wv[i] = ew1[c1 * 7 + i];
    float bias = eb1[c1];
    const float* au = audio + (long)b * kT;
    #pragma unroll
    for (int j = 0; j < 5; j++) {
        int p = s * kHOP - 2 + j;
        float v = 0.f;
        if (p >= 0 && p < kT) {
            float acc = bias;
            #pragma unroll
            for (int i = 0; i < 7; i++) {
                int x = p - 3 + i;
                float a = (x >= 0 && x < kT) ? au[x] : 0.f;
                acc = fmaf(wv[i], a, acc);
            }
            v = fmaxf(acc, 0.f);
        }
        g_S1[(long)m * 1280 + c1 * 5 + j] = v;
    }
}

__global__ void k_reduce(const float* __restrict__ in, float* __restrict__ out,
                         long SP, int nsp, const float* __restrict__ bias, int bmask, int relu) {
    long o = ((long)blockIdx.x * 256 + threadIdx.x) * 4;
    float4 a = *(const float4*)&in[o];
    for (int p = 1; p < nsp; p++) {
        float4 b = *(const float4*)&in[o + p * SP];
        a.x += b.x; a.y += b.y; a.z += b.z; a.w += b.w;
    }
    if (bias) {
        float4 e = *(const float4*)&bias[(int)(o & bmask)];
        a.x += e.x; a.y += e.y; a.z += e.z; a.w += e.w;
    }
    if (relu) {
        a.x = fmaxf(a.x, 0.f); a.y = fmaxf(a.y, 0.f);
        a.z = fmaxf(a.z, 0.f); a.w = fmaxf(a.w, 0.f);
    }
    *(float4*)&out[o] = a;
}

__global__ void k_im2col() {
    int m = blockIdx.x; int b = m / kS, s = m % kS;
    for (int kk = threadIdx.x; kk < 1536; kk += blockDim.x) {
        int c2 = kk / 3, j = kk % 3;
        int s2 = s - 1 + j;
        g_X[(long)m * 1536 + kk] =
            (s2 >= 0 && s2 < kS) ? g_h2[(long)(b * kS + s2) * 512 + c2] : 0.f;
    }
}

__global__ void k_cbnorm(const float* __restrict__ cb) {
    int row = blockIdx.x * 8 + (threadIdx.x >> 5), lane = threadIdx.x & 31;
    const float* p = cb + (long)row * kDIM;
    float acc = 0.f;
    for (int d = lane; d < kDIM; d += 32) { float v = p[d]; acc = fmaf(v, v, acc); }
    #pragma unroll
    for (int o = 16; o > 0; o >>= 1) acc += __shfl_down_sync(0xffffffffu, acc, o);
    if (!lane) g_cbn[row] = acc;
}

__global__ void k_argmin() {
    int row = blockIdx.x, k = row / kBS;
    const float* sc = g_sc + (long)row * kVOC;
    const float* cn = g_cbn + k * kVOC;
    float best = 3.4e38f; int bi = 0;
    for (int v = threadIdx.x; v < kVOC; v += 256) {
        float d = cn[v] - 2.f * sc[v];
        if (d < best) { best = d; bi = v; }
    }
    __shared__ float sv[256]; __shared__ int si[256];
    sv[threadIdx.x] = best; si[threadIdx.x] = bi;
    __syncthreads();
    for (int st = 128; st > 0; st >>= 1) {
        if (threadIdx.x < st) {
            float o = sv[threadIdx.x + st]; int oi = si[threadIdx.x + st];
            if (o < sv[threadIdx.x] || (o == sv[threadIdx.x] && oi < si[threadIdx.x])) {
                sv[threadIdx.x] = o; si[threadIdx.x] = oi;
            }
        }
        __syncthreads();
    }
    if (!threadIdx.x) g_code[row] = si[0];
}

__global__ void k_gather(const float* __restrict__ cb) {
    int m = blockIdx.x;
    for (int n = threadIdx.x * 4; n < kCH3; n += blockDim.x * 4) {
        int k = n >> 9, d = n & 511;
        int code = g_code[k * kBS + m];
        *(float4*)&g_q[(long)m * kCH3 + n] =
            *(const float4*)&cb[((long)k * kVOC + code) * kDIM + d];
    }
}

__global__ void k_w2r(const float* __restrict__ dw2) {
    long i = (long)blockIdx.x * blockDim.x + threadIdx.x;
    if (i < 256L * 2560) {
        int cp = (int)(i / 2560), r = (int)(i % 2560);
        g_W2r[i] = dw2[(long)cp * 2560 + (r % 512) * 5 + r / 512];
    }
}

__global__ void k_awin(const float* __restrict__ db1) {
    int m = blockIdx.x; int s = m % kS;
    const long SP = (long)kBS * 2560;
    for (int i = threadIdx.x; i < 13 * 512; i += blockDim.x) {
        int off = i / 512 - 6; int o = i & 511;
        long t = (long)s * kHOP + off;
        float v = 0.f;
        if (t >= 0 && t < kL) {
            if (off >= -2 && off <= 2) {
                long idx = (long)m * 2560 + o * 5 + (off + 2);
                float c2 = g_C2p[idx] + g_C2p[idx + SP] + g_C2p[idx + 2 * SP] + g_C2p[idx + 3 * SP];
                v = fmaxf(c2 + db1[o], 0.f);
            } else v = fmaxf(db1[o], 0.f);
        }
        g_awin[(long)m * 6656 + i] = v;
    }
}

__global__ void k_bg2(const float* __restrict__ dw2, const float* __restrict__ db1,
                      const float* __restrict__ db2) {
    int cp = blockIdx.x, tid = threadIdx.x;
    float acc = 0.f;
    for (int kk = tid; kk < 2560; kk += 256)
        acc = fmaf(dw2[(long)cp * 2560 + kk], fmaxf(db1[kk / 5], 0.f), acc);
    __shared__ float red[256];
    red[tid] = acc; __syncthreads();
    for (int st = 128; st; st >>= 1) { if (tid < st) red[tid] += red[tid + st]; __syncthreads(); }
    if (!tid) g_bg2[cp] = fmaxf(red[0] + db2[cp], 0.f);
}

__global__ void k_outbg(const float* __restrict__ dw3, const float* __restrict__ db3) {
    __shared__ float red[256];
    int c = threadIdx.x;
    float a = 0.f;
    #pragma unroll
    for (int j = 0; j < 7; j++) a += dw3[c * 7 + j];
    red[c] = a * g_bg2[c];
    __syncthreads();
    for (int st = 128; st; st >>= 1) { if (c < st) red[c] += red[c + st]; __syncthreads(); }
    if (!c) g_outbg = tanhf(red[0] + db3[0]);
}

__global__ void k_fill(float* __restrict__ out, long n) {
    long i = (long)blockIdx.x * 256 + threadIdx.x;
    if (i < n) out[i] = g_outbg;
}

__global__ __launch_bounds__(256) void k_final(
    float* __restrict__ out, const float* __restrict__ dw3, const float* __restrict__ db3) {
    int m = blockIdx.x; int b = m / kS, s = m % kS;
    int tid = threadIdx.x, g = tid >> 4, l = tid & 15;
    int r3 = g - 7;
    long t = (long)s * kHOP + r3;
    bool active = (g < 15) && t >= 0 && t < kL;
    float acc = 0.f;
    if (g < 15) {
        for (int c = l; c < 256; c += 16) {
            #pragma unroll
            for (int j = 0; j < 7; j++) {
                int off = r3 - 3 + j;
                long tt = (long)s * kHOP + off;
                float a2;
                if (tt < 0 || tt >= kL) a2 = 0.f;
                else if (off >= -4 && off <= 4)
                    a2 = g_C3[((long)m * 9 + off + 4) * 256 + c];
                else a2 = g_bg2[c];
                acc = fmaf(dw3[c * 7 + j], a2, acc);
            }
        }
    }
    #pragma unroll
    for (int o = 8; o > 0; o >>= 1) acc += __shfl_down_sync(0xffffffffu, acc, o, 16);
    if (active && l == 0) out[(long)b * kL + t] = tanhf(acc + db3[0]);
}

// ---------------- launch ----------------
extern "C" void kernel_launch(void* const* d_in, const int* in_sizes, int n_in,
                              void* d_out, int out_size) {
    const float* audio = (const float*)d_in[0];
    const float* cb    = (const float*)d_in[1];
    const float* ew1   = (const float*)d_in[2];
    const float* eb1   = (const float*)d_in[3];
    const float* ew2   = (const float*)d_in[4];
    const float* eb2   = (const float*)d_in[5];
    const float* ew3   = (const float*)d_in[6];
    const float* eb3   = (const float*)d_in[7];
    const float* dw1   = (const float*)d_in[8];
    const float* db1   = (const float*)d_in[9];
    const float* dw2   = (const float*)d_in[10];
    const float* db2   = (const float*)d_in[11];
    const float* dw3   = (const float*)d_in[12];
    const float* db3   = (const float*)d_in[13];
    float* out = (float*)d_out;

    cudaFuncSetAttribute(hmma_gemm<0>, cudaFuncAttributeMaxDynamicSharedMemorySize, SMEM_DYN);
    cudaFuncSetAttribute(hmma_gemm<1>, cudaFuncAttributeMaxDynamicSharedMemorySize, SMEM_DYN);

    void *pS1, *pH2p, *pH2, *pX, *pEmb, *pSc, *pQ, *pC2p, *pAwin, *pW2r, *pC3p, *pC3;
    cudaGetSymbolAddress(&pS1, g_S1);   cudaGetSymbolAddress(&pH2p, g_h2p);
    cudaGetSymbolAddress(&pH2, g_h2);   cudaGetSymbolAddress(&pX, g_X);
    cudaGetSymbolAddress(&pEmb, g_emb); cudaGetSymbolAddress(&pSc, g_sc);
    cudaGetSymbolAddress(&pQ, g_q);     cudaGetSymbolAddress(&pC2p, g_C2p);
    cudaGetSymbolAddress(&pAwin, g_awin); cudaGetSymbolAddress(&pW2r, g_W2r);
    cudaGetSymbolAddress(&pC3p, g_C3p); cudaGetSymbolAddress(&pC3, g_C3);

    // weight-only prep
    k_cbnorm<<<kNCB * kVOC / 8, 256>>>(cb);
    k_w2r<<<(256 * 2560 + 255) / 256, 256>>>(dw2);
    k_bg2<<<256, 256>>>(dw2, db1, db2);
    k_outbg<<<1, 256>>>(dw3, db3);
    k_fill<<<(int)((kB * kL + 255) / 256), 256>>>(out, kB * kL);

    // encoder: conv1 windows -> conv2 GEMM (splitK8) -> reduce -> im2col -> conv3 GEMM
    k_prep1<<<kBS, 256>>>(audio, ew1, eb1);
    hmma_gemm<0><<<dim3(4, 2, 8), 256, SMEM_DYN>>>(
        (const float*)pS1, ew2, (float*)pH2p, 160, 1280,
        BIGL, 0, 1280, 0, 0, (long)kBS * 512, 160, 512, BIGL, 0, nullptr, 0);
    k_reduce<<<kBS * 512 / 1024, 256>>>((const float*)pH2p, (float*)pH2,
                                        (long)kBS * 512, 8, eb2, 511, 1);
    k_im2col<<<kBS, 256>>>();
    hmma_gemm<0><<<dim3(56, 2, 1), 256, SMEM_DYN>>>(
        (const float*)pX, ew3, (float*)pEmb, 1536, 1536,
        BIGL, 0, 1536, 0, 0, 0, 0, 512, 512, (long)kBS * 512, eb3, 0);

    // VQ
    hmma_gemm<0><<<dim3(8, 2, 14), 256, SMEM_DYN>>>(
        (const float*)pEmb, cb, (float*)pSc, 512, 512,
        BIGL, 0, 512, (long)kBS * 512, (long)kVOC * 512, (long)kBS * kVOC, 0,
        kVOC, BIGL, 0, nullptr, 0);
    k_argmin<<<kNCB * kBS, 256>>>();
    k_gather<<<kBS, 256>>>(cb);

    // decoder conv_transpose specials: splitK4, partials summed in k_awin
    hmma_gemm<1><<<dim3(20, 2, 4), 256, SMEM_DYN>>>(
        (const float*)pQ, dw1, (float*)pC2p, 1792, 2560,
        BIGL, 0, kCH3, 0, 0, (long)kBS * 2560, 1792, 2560, BIGL, 0, nullptr, 0);
    k_awin<<<kBS, 256>>>(db1);

    // decoder conv2 specials: splitK4 -> reduce(+db2,relu)
    hmma_gemm<0><<<dim3(2, 18, 4), 256, SMEM_DYN>>>(
        (const float*)pAwin, (const float*)pW2r, (float*)pC3p, 640, 2560,
        9, 6656, 512, 0, 0, 2304L * 256, 640, 256, BIGL, 0, nullptr, 0);
    k_reduce<<<2304 * 256 / 1024, 256>>>((const float*)pC3p, (float*)pC3,
                                         2304L * 256, 4, db2, 255, 1);

    // final conv3 specials
    k_final<<<kBS, 256>>>(out, dw3, db3);
}

// round 7
// speedup vs baseline: 2.2475x; 1.0876x over previous
#include <cuda_runtime.h>
#include <math.h>
#include <stdint.h>

typedef unsigned long long ull;

// ---------------- problem constants ----------------
constexpr int kB = 2, kT = 98304, kS = 128, kHOP = 768, kNCB = 14;
constexpr int kDIM = 512, kVOC = 1024, kCH3 = kNCB * kDIM;   // 7168
constexpr long kL = 97537;
constexpr int kBS = kB * kS;        // 256
constexpr long BIGL = 1L << 40;

// ---------------- device scratch ----------------
__device__ float g_S1  [kBS * 1280];
__device__ float g_h2p [8 * kBS * 512];
__device__ float g_X   [kBS * 1536];
__device__ float g_emb [kNCB * kBS * kDIM];
__device__ float g_cbn [kNCB * kVOC];
__device__ ull   g_best[kNCB * kBS];            // packed (dist key | code)
__device__ float g_C2p [4 * kBS * 2560];
__device__ float g_awin[kBS * 13 * 512];
__device__ float g_W2r [256 * 2560];
__device__ float g_C3p [4 * 2304 * 256];
__device__ float g_bg2 [256];

// =================== HMMA bf16 split-precision GEMM ===================
constexpr int KC = 32;
constexpr int PITCH_B = 80;
constexpr int TILE_BYTES = 128 * PITCH_B;
constexpr int STAGE = 4 * TILE_BYTES;
constexpr int SMEM_DYN = 2 * STAGE;              // 81920

__device__ __forceinline__ uint32_t s2u(const void* p) {
    uint32_t a;
    asm("{ .reg .u64 t; cvta.to.shared.u64 t, %1; cvt.u32.u64 %0, t; }" : "=r"(a) : "l"(p));
    return a;
}
__device__ __forceinline__ uint32_t pkbf2(float lo, float hi) {
    uint32_t r;
    asm("cvt.rn.bf16x2.f32 %0, %1, %2;" : "=r"(r) : "f"(hi), "f"(lo));
    return r;
}
__device__ __forceinline__ void cvt8(float4 x0, float4 x1, uint4& h, uint4& l) {
    h.x = pkbf2(x0.x, x0.y); h.y = pkbf2(x0.z, x0.w);
    h.z = pkbf2(x1.x, x1.y); h.w = pkbf2(x1.z, x1.w);
    l.x = pkbf2(x0.x - __uint_as_float(h.x << 16), x0.y - __uint_as_float(h.x & 0xffff0000u));
    l.y = pkbf2(x0.z - __uint_as_float(h.y << 16), x0.w - __uint_as_float(h.y & 0xffff0000u));
    l.z = pkbf2(x1.x - __uint_as_float(h.z << 16), x1.y - __uint_as_float(h.z & 0xffff0000u));
    l.w = pkbf2(x1.z - __uint_as_float(h.w << 16), x1.w - __uint_as_float(h.w & 0xffff0000u));
}
__device__ __forceinline__ void ldsm4(uint32_t a, uint32_t& r0, uint32_t& r1,
                                      uint32_t& r2, uint32_t& r3) {
    asm volatile("ldmatrix.sync.aligned.m8n8.x4.shared.b16 {%0,%1,%2,%3},[%4];"
                 : "=r"(r0), "=r"(r1), "=r"(r2), "=r"(r3) : "r"(a));
}
__device__ __forceinline__ void mma16816(float* d, const uint32_t* a, const uint32_t* b) {
    asm volatile(
        "mma.sync.aligned.m16n8k16.row.col.f32.bf16.bf16.f32 "
        "{%0,%1,%2,%3},{%4,%5,%6,%7},{%8,%9},{%0,%1,%2,%3};"
        : "+f"(d[0]), "+f"(d[1]), "+f"(d[2]), "+f"(d[3])
        : "r"(a[0]), "r"(a[1]), "r"(a[2]), "r"(a[3]), "r"(b[0]), "r"(b[1]));
}
__device__ __forceinline__ ull packkey(float f, int n) {
    uint32_t b = __float_as_uint(f);
    uint32_t key = (b & 0x80000000u) ? ~b : (b | 0x80000000u);
    return ((ull)key << 32) | (uint32_t)n;
}
__device__ __forceinline__ ull umin2(ull a, ull b) { return a < b ? a : b; }

// C[m,n] = sum_k A(m)[k]*B(n,k).
// BNN=0: B[N,ldb] row-major. BNN=1: B[K,ldb] row-major AND A is the codebook
// (gather path: A row m of codebook cbk uses code from g_best[cbk*256+m]).
// A row m base = (m/adiv)*aout + (m%adiv)*ain (BNN=0 only).
// z: A+=z*zA, B+=z*zB, C+=z*zC, kbase=z*zK.
// C: Cb = C + (n0/cdiv)*cout; element [mrow*ldc + n0%cdiv + col]; bias[n]; relu.
// If best != nullptr: skip C write; fused VQ argmin using cbn[z*kVOC+n].
template <int BNN>
__global__ __launch_bounds__(256, 1)
void hmma_gemm(const float* __restrict__ A, const float* __restrict__ B,
               float* __restrict__ C, int Klen, int ldb,
               long adiv, long aout, long ain, long zA, long zB, long zC, long zK,
               int ldc, long cdiv, long cout, const float* __restrict__ bias, int relu,
               const float* __restrict__ cbn, ull* __restrict__ best) {
    extern __shared__ __align__(16) char smem[];
    A += (long)blockIdx.z * zA; B += (long)blockIdx.z * zB; C += (long)blockIdx.z * zC;
    long kbase = (long)blockIdx.z * zK;
    int m0 = blockIdx.y * 128, n0 = blockIdx.x * 128;
    int tid = threadIdx.x, lane = tid & 31, wid = tid >> 5;
    int wm = wid & 1, wn = wid >> 1;
    uint32_t sbase = s2u(smem);

    int akg = tid & 3, ar = tid >> 2;
    long arow[2];
    #pragma unroll
    for (int i = 0; i < 2; i++) {
        long m = m0 + ar + i * 64;
        arow[i] = (m / adiv) * aout + (m % adiv) * ain;
    }
    int bkg = tid & 3, br = tid >> 2;
    int bn = tid & 127, bkq = tid >> 7;

    float acc[4][4][4];
    #pragma unroll
    for (int i = 0; i < 4; i++)
        #pragma unroll
        for (int j = 0; j < 4; j++)
            #pragma unroll
            for (int r = 0; r < 4; r++) acc[i][j][r] = 0.f;

    float4 sa[2][2];
    float4 sb[2][2];
    float  sx[16];

#define LOADA(kc) {                                                          \
    if (BNN == 1) {                                                          \
        int cbk = (int)((kc) >> 9), kin = (int)((kc) & 511);                 \
        _Pragma("unroll")                                                    \
        for (int i = 0; i < 2; i++) {                                        \
            uint32_t code = (uint32_t)g_best[cbk * 256 + m0 + ar + i * 64];  \
            const float* p = A + ((long)cbk * kVOC + code) * 512 + kin + akg * 8; \
            sa[i][0] = *(const float4*)p; sa[i][1] = *(const float4*)(p + 4); \
        }                                                                    \
    } else {                                                                 \
        _Pragma("unroll")                                                    \
        for (int i = 0; i < 2; i++) {                                        \
            const float* p = A + arow[i] + (kc) + akg * 8;                   \
            sa[i][0] = *(const float4*)p; sa[i][1] = *(const float4*)(p + 4); \
        }                                                                    \
    } }
#define STSA(buf) {                                                          \
    _Pragma("unroll")                                                        \
    for (int i = 0; i < 2; i++) {                                            \
        uint4 h, l; cvt8(sa[i][0], sa[i][1], h, l);                          \
        uint32_t off = sbase + (buf) * STAGE + (ar + i * 64) * PITCH_B + akg * 16; \
        asm volatile("st.shared.v4.b32 [%0],{%1,%2,%3,%4};" ::               \
            "r"(off), "r"(h.x), "r"(h.y), "r"(h.z), "r"(h.w));               \
        asm volatile("st.shared.v4.b32 [%0],{%1,%2,%3,%4};" ::               \
            "r"(off + TILE_BYTES), "r"(l.x), "r"(l.y), "r"(l.z), "r"(l.w));  \
    } }
#define LOADB_NT(kc) {                                                       \
    _Pragma("unroll")                                                        \
    for (int i = 0; i < 2; i++) {                                            \
        const float* p = B + (long)(n0 + br + i * 64) * ldb + (kc) + bkg * 8; \
        sb[i][0] = *(const float4*)p; sb[i][1] = *(const float4*)(p + 4);    \
    } }
#define STSB_NT(buf) {                                                       \
    _Pragma("unroll")                                                        \
    for (int i = 0; i < 2; i++) {                                            \
        uint4 h, l; cvt8(sb[i][0], sb[i][1], h, l);                          \
        uint32_t off = sbase + (buf) * STAGE + 2 * TILE_BYTES                \
                     + (br + i * 64) * PITCH_B + bkg * 16;                   \
        asm volatile("st.shared.v4.b32 [%0],{%1,%2,%3,%4};" ::               \
            "r"(off), "r"(h.x), "r"(h.y), "r"(h.z), "r"(h.w));               \
        asm volatile("st.shared.v4.b32 [%0],{%1,%2,%3,%4};" ::               \
            "r"(off + TILE_BYTES), "r"(l.x), "r"(l.y), "r"(l.z), "r"(l.w));  \
    } }
#define LOADB_NN(kc) {                                                       \
    _Pragma("unroll")                                                        \
    for (int j = 0; j < 16; j++)                                             \
        sx[j] = B[((kc) + bkq * 16 + j) * (long)ldb + n0 + bn];              \
    }
#define STSB_NN(buf) {                                                       \
    uint32_t off = sbase + (buf) * STAGE + 2 * TILE_BYTES                    \
                 + bn * PITCH_B + bkq * 32;                                  \
    uint4 h, l;                                                              \
    cvt8(make_float4(sx[0], sx[1], sx[2], sx[3]),                            \
         make_float4(sx[4], sx[5], sx[6], sx[7]), h, l);                     \
    asm volatile("st.shared.v4.b32 [%0],{%1,%2,%3,%4};" ::                   \
        "r"(off), "r"(h.x), "r"(h.y), "r"(h.z), "r"(h.w));                   \
    asm volatile("st.shared.v4.b32 [%0],{%1,%2,%3,%4};" ::                   \
        "r"(off + TILE_BYTES), "r"(l.x), "r"(l.y), "r"(l.z), "r"(l.w));      \
    cvt8(make_float4(sx[8], sx[9], sx[10], sx[11]),                          \
         make_float4(sx[12], sx[13], sx[14], sx[15]), h, l);                 \
    asm volatile("st.shared.v4.b32 [%0],{%1,%2,%3,%4};" ::                   \
        "r"(off + 16), "r"(h.x), "r"(h.y), "r"(h.z), "r"(h.w));              \
    asm volatile("st.shared.v4.b32 [%0],{%1,%2,%3,%4};" ::                   \
        "r"(off + TILE_BYTES + 16), "r"(l.x), "r"(l.y), "r"(l.z), "r"(l.w)); \
    }

    LOADA(kbase)
    if (!BNN) { LOADB_NT(kbase) } else { LOADB_NN(kbase) }
    STSA(0)
    if (!BNN) { STSB_NT(0) } else { STSB_NN(0) }
    __syncthreads();

    int T = Klen / KC;
    int j8 = lane >> 3, r8 = lane & 7;
    for (int t = 0; t < T; t++) {
        int cur = t & 1;
        if (t + 1 < T) {
            long kc = kbase + (long)(t + 1) * KC;
            LOADA(kc)
            if (!BNN) { LOADB_NT(kc) } else { LOADB_NN(kc) }
        }
        uint32_t uA = sbase + cur * STAGE;
        uint32_t uB = uA + 2 * TILE_BYTES;
        #pragma unroll
        for (int ks = 0; ks < 2; ks++) {
            uint32_t ah[4][4], al[4][4], bh[4][2], bl[4][2];
            #pragma unroll
            for (int mf = 0; mf < 4; mf++) {
                uint32_t off = (uint32_t)((wm * 64 + mf * 16 + ((j8 & 1) << 3) + r8) * PITCH_B
                                          + ks * 32 + ((j8 >> 1) << 4));
                ldsm4(uA + off, ah[mf][0], ah[mf][1], ah[mf][2], ah[mf][3]);
                ldsm4(uA + TILE_BYTES + off, al[mf][0], al[mf][1], al[mf][2], al[mf][3]);
            }
            #pragma unroll
            for (int fp = 0; fp < 2; fp++) {
                uint32_t off = (uint32_t)((wn * 32 + fp * 16 + ((j8 >> 1) << 3) + r8) * PITCH_B
                                          + ks * 32 + ((j8 & 1) << 4));
                uint32_t t0, t1, t2, t3;
                ldsm4(uB + off, t0, t1, t2, t3);
                bh[fp * 2][0] = t0; bh[fp * 2][1] = t1;
                bh[fp * 2 + 1][0] = t2; bh[fp * 2 + 1][1] = t3;
                ldsm4(uB + TILE_BYTES + off, t0, t1, t2, t3);
                bl[fp * 2][0] = t0; bl[fp * 2][1] = t1;
                bl[fp * 2 + 1][0] = t2; bl[fp * 2 + 1][1] = t3;
            }
            #pragma unroll
            for (int mf = 0; mf < 4; mf++)
                #pragma unroll
                for (int nf = 0; nf < 4; nf++) {
                    mma16816(acc[mf][nf], ah[mf], bh[nf]);
                    mma16816(acc[mf][nf], ah[mf], bl[nf]);
                    mma16816(acc[mf][nf], al[mf], bh[nf]);
                }
        }
        if (t + 1 < T) {
            STSA(1 - cur)
            if (!BNN) { STSB_NT(1 - cur) } else { STSB_NN(1 - cur) }
        }
        __syncthreads();
    }

    int mrow_base = m0 + wm * 64 + (lane >> 2);
    int ncol_base = wn * 32 + (lane & 3) * 2;

    if (best) {
        // fused VQ argmin epilogue
        float cv[8];
        #pragma unroll
        for (int nf = 0; nf < 4; nf++) {
            int ncol = ncol_base + nf * 8;
            cv[nf * 2 + 0] = cbn[(long)blockIdx.z * kVOC + n0 + ncol];
            cv[nf * 2 + 1] = cbn[(long)blockIdx.z * kVOC + n0 + ncol + 1];
        }
        #pragma unroll
        for (int mf = 0; mf < 4; mf++)
            #pragma unroll
            for (int h = 0; h < 2; h++) {
                ull bp = ~0ull;
                #pragma unroll
                for (int nf = 0; nf < 4; nf++) {
                    int ncol = ncol_base + nf * 8;
                    float d0 = cv[nf * 2 + 0] - 2.f * acc[mf][nf][h * 2 + 0];
                    float d1 = cv[nf * 2 + 1] - 2.f * acc[mf][nf][h * 2 + 1];
                    bp = umin2(bp, umin2(packkey(d0, n0 + ncol), packkey(d1, n0 + ncol + 1)));
                }
                bp = umin2(bp, (ull)__shfl_xor_sync(0xffffffffu, (long long)bp, 1));
                bp = umin2(bp, (ull)__shfl_xor_sync(0xffffffffu, (long long)bp, 2));
                if ((lane & 3) == 0)
                    atomicMin(&best[(long)blockIdx.z * 256 + mrow_base + mf * 16 + h * 8], bp);
            }
        return;
    }

    float* Cb = C + (long)(n0 / cdiv) * cout;
    long ncb0 = n0 % cdiv;
    #pragma unroll
    for (int mf = 0; mf < 4; mf++)
        #pragma unroll
        for (int nf = 0; nf < 4; nf++) {
            int ncol = ncol_base + nf * 8;
            float bx = 0.f, by = 0.f;
            if (bias) { bx = bias[n0 + ncol]; by = bias[n0 + ncol + 1]; }
            #pragma unroll
            for (int h = 0; h < 2; h++) {
                float vx = acc[mf][nf][h * 2 + 0] + bx;
                float vy = acc[mf][nf][h * 2 + 1] + by;
                if (relu) { vx = fmaxf(vx, 0.f); vy = fmaxf(vy, 0.f); }
                long row = mrow_base + mf * 16 + h * 8;
                *(float2*)&Cb[row * (long)ldc + ncb0 + ncol] = make_float2(vx, vy);
            }
        }
}

// ---------------- merged weight-prep kernel ----------------
__global__ void k_prep(const float* __restrict__ cb, const float* __restrict__ dw2,
                       const float* __restrict__ db1, const float* __restrict__ db2) {
    int blk = blockIdx.x, tid = threadIdx.x;
    if (blk < 1792) {                      // codebook norms
        int row = blk * 8 + (tid >> 5), lane = tid & 31;
        const float* p = cb + (long)row * kDIM;
        float acc = 0.f;
        for (int d = lane; d < kDIM; d += 32) { float v = p[d]; acc = fmaf(v, v, acc); }
        #pragma unroll
        for (int o = 16; o > 0; o >>= 1) acc += __shfl_down_sync(0xffffffffu, acc, o);
        if (!lane) g_cbn[row] = acc;
    } else if (blk < 1792 + 2560) {        // dw2 rearrange
        long i = (long)(blk - 1792) * 256 + tid;
        int cp = (int)(i / 2560), r = (int)(i % 2560);
        g_W2r[i] = dw2[(long)cp * 2560 + (r % 512) * 5 + r / 512];
    } else if (blk < 1792 + 2560 + 256) {  // bg2
        int cp = blk - (1792 + 2560);
        float acc = 0.f;
        for (int kk = tid; kk < 2560; kk += 256)
            acc = fmaf(dw2[(long)cp * 2560 + kk], fmaxf(db1[kk / 5], 0.f), acc);
        __shared__ float red[256];
        red[tid] = acc; __syncthreads();
        for (int st = 128; st; st >>= 1) { if (tid < st) red[tid] += red[tid + st]; __syncthreads(); }
        if (!tid) g_bg2[cp] = fmaxf(red[0] + db2[cp], 0.f);
    } else {                               // init g_best
        for (int i = tid; i < kNCB * kBS; i += 256) g_best[i] = ~0ull;
    }
}

// ---------------- fill with fused background compute ----------------
__global__ __launch_bounds__(256) void k_fill(float* __restrict__ out, long n,
                                              const float* __restrict__ dw3,
                                              const float* __restrict__ db3) {
    __shared__ float red[256];
    int c = threadIdx.x;
    float a = 0.f;
    #pragma unroll
    for (int j = 0; j < 7; j++) a += dw3[c * 7 + j];
    red[c] = a * g_bg2[c];
    __syncthreads();
    for (int st = 128; st; st >>= 1) { if (c < st) red[c] += red[c + st]; __syncthreads(); }
    float outv = tanhf(red[0] + db3[0]);
    long i = (long)blockIdx.x * 256 + threadIdx.x;
    if (i < n) out[i] = outv;
}

// ---------------- conv1 window builder ----------------
__global__ __launch_bounds__(256) void k_prep1(
    const float* __restrict__ audio, const float* __restrict__ ew1, const float* __restrict__ eb1) {
    int m = blockIdx.x; int b = m / kS, s = m % kS;
    int c1 = threadIdx.x;
    float wv[7];
    #pragma unroll
    for (int i = 0; i < 7; i++) wv[i] = ew1[c1 * 7 + i];
    float bias = eb1[c1];
    const float* au = audio + (long)b * kT;
    #pragma unroll
    for (int j = 0; j < 5; j++) {
        int p = s * kHOP - 2 + j;
        float v = 0.f;
        if (p >= 0 && p < kT) {
            float acc = bias;
            #pragma unroll
            for (int i = 0; i < 7; i++) {
                int x = p - 3 + i;
                float a = (x >= 0 && x < kT) ? au[x] : 0.f;
                acc = fmaf(wv[i], a, acc);
            }
            v = fmaxf(acc, 0.f);
        }
        g_S1[(long)m * 1280 + c1 * 5 + j] = v;
    }
}

// ---------------- im2col with fused h2 splitK-reduce + eb2 + relu ----------------
__global__ void k_im2col(const float* __restrict__ eb2) {
    int m = blockIdx.x; int b = m / kS, s = m % kS;
    const long SP = (long)kBS * 512;
    for (int kk = threadIdx.x; kk < 1536; kk += blockDim.x) {
        int c2 = kk / 3, j = kk % 3;
        int s2 = s - 1 + j;
        float v = 0.f;
        if (s2 >= 0 && s2 < kS) {
            long idx = (long)(b * kS + s2) * 512 + c2;
            float acc = eb2[c2];
            #pragma unroll
            for (int p = 0; p < 8; p++) acc += g_h2p[idx + p * SP];
            v = fmaxf(acc, 0.f);
        }
        g_X[(long)m * 1536 + kk] = v;
    }
}

// ---------------- a-window (sums conv_t splitK partials) ----------------
__global__ void k_awin(const float* __restrict__ db1) {
    int m = blockIdx.x; int s = m % kS;
    const long SP = (long)kBS * 2560;
    for (int i = threadIdx.x; i < 13 * 512; i += blockDim.x) {
        int off = i / 512 - 6; int o = i & 511;
        long t = (long)s * kHOP + off;
        float v = 0.f;
        if (t >= 0 && t < kL) {
            if (off >= -2 && off <= 2) {
                long idx = (long)m * 2560 + o * 5 + (off + 2);
                float c2 = g_C2p[idx] + g_C2p[idx + SP] + g_C2p[idx + 2 * SP] + g_C2p[idx + 3 * SP];
                v = fmaxf(c2 + db1[o], 0.f);
            } else v = fmaxf(db1[o], 0.f);
        }
        g_awin[(long)m * 6656 + i] = v;
    }
}

// ---------------- final conv3 with fused C3 splitK-reduce + db2 + relu ----------------
__global__ __launch_bounds__(256) void k_final(
    float* __restrict__ out, const float* __restrict__ db2,
    const float* __restrict__ dw3, const float* __restrict__ db3) {
    int m = blockIdx.x; int b = m / kS, s = m % kS;
    int tid = threadIdx.x;
    __shared__ float win[9 * 256];
    __shared__ float sbg[256];
    const long SP = 2304L * 256;
    for (int idx = tid; idx < 2304; idx += 256) {
        long base = ((long)m * 9 + idx / 256) * 256 + (idx & 255);
        float v = g_C3p[base] + g_C3p[base + SP] + g_C3p[base + 2 * SP] + g_C3p[base + 3 * SP]
                + db2[idx & 255];
        win[idx] = fmaxf(v, 0.f);
    }
    sbg[tid] = g_bg2[tid];
    __syncthreads();

    int g = tid >> 4, l = tid & 15;
    int r3 = g - 7;
    long t = (long)s * kHOP + r3;
    bool active = (g < 15) && t >= 0 && t < kL;
    float acc = 0.f;
    if (g < 15) {
        for (int c = l; c < 256; c += 16) {
            #pragma unroll
            for (int j = 0; j < 7; j++) {
                int off = r3 - 3 + j;
                long tt = (long)s * kHOP + off;
                float a2;
                if (tt < 0 || tt >= kL) a2 = 0.f;
                else if (off >= -4 && off <= 4) a2 = win[(off + 4) * 256 + c];
                else a2 = sbg[c];
                acc = fmaf(dw3[c * 7 + j], a2, acc);
            }
        }
    }
    #pragma unroll
    for (int o = 8; o > 0; o >>= 1) acc += __shfl_down_sync(0xffffffffu, acc, o, 16);
    if (active && l == 0) out[(long)b * kL + t] = tanhf(acc + db3[0]);
}

// ---------------- launch ----------------
extern "C" void kernel_launch(void* const* d_in, const int* in_sizes, int n_in,
                              void* d_out, int out_size) {
    const float* audio = (const float*)d_in[0];
    const float* cb    = (const float*)d_in[1];
    const float* ew1   = (const float*)d_in[2];
    const float* eb1   = (const float*)d_in[3];
    const float* ew2   = (const float*)d_in[4];
    const float* eb2   = (const float*)d_in[5];
    const float* ew3   = (const float*)d_in[6];
    const float* eb3   = (const float*)d_in[7];
    const float* dw1   = (const float*)d_in[8];
    const float* db1   = (const float*)d_in[9];
    const float* dw2   = (const float*)d_in[10];
    const float* db2   = (const float*)d_in[11];
    const float* dw3   = (const float*)d_in[12];
    const float* db3   = (const float*)d_in[13];
    float* out = (float*)d_out;

    cudaFuncSetAttribute(hmma_gemm<0>, cudaFuncAttributeMaxDynamicSharedMemorySize, SMEM_DYN);
    cudaFuncSetAttribute(hmma_gemm<1>, cudaFuncAttributeMaxDynamicSharedMemorySize, SMEM_DYN);

    void *pS1, *pH2p, *pX, *pEmb, *pCbn, *pBest, *pC2p, *pAwin, *pW2r, *pC3p;
    cudaGetSymbolAddress(&pS1, g_S1);   cudaGetSymbolAddress(&pH2p, g_h2p);
    cudaGetSymbolAddress(&pX, g_X);     cudaGetSymbolAddress(&pEmb, g_emb);
    cudaGetSymbolAddress(&pCbn, g_cbn); cudaGetSymbolAddress(&pBest, g_best);
    cudaGetSymbolAddress(&pC2p, g_C2p); cudaGetSymbolAddress(&pAwin, g_awin);
    cudaGetSymbolAddress(&pW2r, g_W2r); cudaGetSymbolAddress(&pC3p, g_C3p);

    // weight prep (cbnorm + w2r + bg2 + best-init), then background fill
    k_prep<<<1792 + 2560 + 256 + 1, 256>>>(cb, dw2, db1, db2);
    k_fill<<<(int)((kB * kL + 255) / 256), 256>>>(out, kB * kL, dw3, db3);

    // encoder
    k_prep1<<<kBS, 256>>>(audio, ew1, eb1);
    hmma_gemm<0><<<dim3(4, 2, 8), 256, SMEM_DYN>>>(
        (const float*)pS1, ew2, (float*)pH2p, 160, 1280,
        BIGL, 0, 1280, 0, 0, (long)kBS * 512, 160, 512, BIGL, 0, nullptr, 0,
        nullptr, nullptr);
    k_im2col<<<kBS, 256>>>(eb2);
    hmma_gemm<0><<<dim3(56, 2, 1), 256, SMEM_DYN>>>(
        (const float*)pX, ew3, (float*)pEmb, 1536, 1536,
        BIGL, 0, 1536, 0, 0, 0, 0, 512, 512, (long)kBS * 512, eb3, 0,
        nullptr, nullptr);

    // VQ with fused argmin (no score matrix materialized)
    hmma_gemm<0><<<dim3(8, 2, 14), 256, SMEM_DYN>>>(
        (const float*)pEmb, cb, (float*)pEmb /*unused*/, 512, 512,
        BIGL, 0, 512, (long)kBS * 512, (long)kVOC * 512, 0, 0,
        kVOC, BIGL, 0, nullptr, 0, (const float*)pCbn, (ull*)pBest);

    // decoder conv_transpose specials: gather fused into A-producer, splitK4
    hmma_gemm<1><<<dim3(20, 2, 4), 256, SMEM_DYN>>>(
        cb, dw1, (float*)pC2p, 1792, 2560,
        BIGL, 0, kCH3, 0, 0, (long)kBS * 2560, 1792, 2560, BIGL, 0, nullptr, 0,
        nullptr, nullptr);
    k_awin<<<kBS, 256>>>(db1);

    // decoder conv2 specials: splitK4 (reduce fused into k_final)
    hmma_gemm<0><<<dim3(2, 18, 4), 256, SMEM_DYN>>>(
        (const float*)pAwin, (const float*)pW2r, (float*)pC3p, 640, 2560,
        9, 6656, 512, 0, 0, 2304L * 256, 640, 256, BIGL, 0, nullptr, 0,
        nullptr, nullptr);

    // final conv3 specials (fused reduce + relu)
    k_final<<<kBS, 256>>>(out, db2, dw3, db3);
}